// round 11
// baseline (speedup 1.0000x reference)
#include <cuda_runtime.h>
#include <cuda_fp16.h>
#include <math.h>

#define SEQ_L  8192
#define NPAIR  512
#define NBATCH 4
#define FFT_N  16384
#define ROWLEN 1088                 // 1024 + pad
#define SP2(i) ((i) + ((i) >> 4))

// -------- device globals (no cudaMalloc allowed) ----------------------------
__device__ __half2 g_B[(size_t)NBATCH * NPAIR * 16 * 1024];   // 134 MB staging
__device__ float2  g_kf[(size_t)NPAIR * 16 * 1024];           // 67 MB filter table
__constant__ int c_jA[8] = {0, 1, 4, 5, 6, 7, 8, 9};
__constant__ int c_jB[8] = {2, 3, 15, 14, 13, 12, 11, 10};

// ----------------------------- complex helpers ------------------------------
struct C2 { float x, y; };
__device__ __forceinline__ C2 mkc(float a, float b){ C2 r; r.x=a; r.y=b; return r; }
__device__ __forceinline__ C2 cadd(C2 a, C2 b){ return mkc(a.x+b.x, a.y+b.y); }
__device__ __forceinline__ C2 csub(C2 a, C2 b){ return mkc(a.x-b.x, a.y-b.y); }
__device__ __forceinline__ C2 cmul(C2 a, C2 b){ return mkc(a.x*b.x - a.y*b.y, a.x*b.y + a.y*b.x); }
__device__ __forceinline__ C2 cmulc(C2 a, C2 b){ return mkc(a.x*b.x + a.y*b.y, a.y*b.x - a.x*b.y); }
__device__ __forceinline__ C2 mulni(C2 a){ return mkc(a.y, -a.x); }
__device__ __forceinline__ C2 mulpi(C2 a){ return mkc(-a.y, a.x); }

__device__ __forceinline__ C2 w16c(int n) {
    const float C[10] = {1.f, 0.92387953f, 0.70710678f, 0.38268343f, 0.f,
                         -0.38268343f, -0.70710678f, -0.92387953f, -1.f, -0.92387953f};
    const float S[10] = {0.f, -0.38268343f, -0.70710678f, -0.92387953f, -1.f,
                         -0.92387953f, -0.70710678f, -0.38268343f, 0.f, 0.38268343f};
    return mkc(C[n], S[n]);
}
__device__ __forceinline__ C2 twN(int j) {   // W_16384^j
    float sv, cv; sincospif(-(float)j * (1.0f/8192.0f), &sv, &cv); return mkc(cv, sv);
}
__device__ __forceinline__ C2 tw1k(int j) {  // W_1024^j
    float sv, cv; sincospif(-(float)j * (1.0f/512.0f), &sv, &cv); return mkc(cv, sv);
}
// position of frequency f in the [4,16,16] row storage
// sigma = base-4 digit swap of a 4-bit index
__device__ __forceinline__ int sig4(int x){ return ((x & 3) << 2) | (x >> 2); }
__device__ __forceinline__ int p0f(int f){
    return 256 * (f & 3) + 16 * sig4((f >> 2) & 15) + sig4(f >> 6);
}

// ---------------- register radix-16 (two fused radix-4 layers) --------------
__device__ __forceinline__ void r16_fwd(C2* v, C2 u1) {
    C2 u2 = cmul(u1,u1);
    C2 u3 = cmul(u2,u1);
    #pragma unroll
    for (int q = 0; q < 4; q++) {
        C2 a=v[q], b=v[q+4], c=v[q+8], d=v[q+12];
        C2 t0=cadd(a,c), t1=csub(a,c), t2=cadd(b,d), t3=mulni(csub(b,d));
        v[q] = cadd(t0,t2);
        C2 o1 = cmul(cadd(t1,t3), u1);
        C2 o2 = cmul(csub(t0,t2), u2);
        C2 o3 = cmul(csub(t1,t3), u3);
        if (q) { o1=cmul(o1,w16c(q)); o2=cmul(o2,w16c(2*q)); o3=cmul(o3,w16c(3*q)); }
        v[q+4]=o1; v[q+8]=o2; v[q+12]=o3;
    }
    C2 u4 = cmul(u2,u2);
    C2 u8 = cmul(u4,u4);
    C2 u12 = cmul(u8,u4);
    #pragma unroll
    for (int s = 0; s < 4; s++) {
        C2 a=v[4*s], b=v[4*s+1], c=v[4*s+2], d=v[4*s+3];
        C2 t0=cadd(a,c), t1=csub(a,c), t2=cadd(b,d), t3=mulni(csub(b,d));
        v[4*s]   = cadd(t0,t2);
        v[4*s+1] = cmul(cadd(t1,t3), u4);
        v[4*s+2] = cmul(csub(t0,t2), u8);
        v[4*s+3] = cmul(csub(t1,t3), u12);
    }
}

__device__ __forceinline__ void r16_fwd_zfold(C2* v, C2 u1) {
    C2 u2 = cmul(u1,u1);
    C2 u3 = cmul(u2,u1);
    #pragma unroll
    for (int q = 0; q < 4; q++) {
        C2 a=v[q], b=v[q+4];
        C2 nb = mulni(b);
        C2 o0 = cadd(a,b);
        C2 o1 = cmul(cadd(a,nb), u1);
        C2 o2 = cmul(csub(a,b), u2);
        C2 o3 = cmul(csub(a,nb), u3);
        if (q) { o1=cmul(o1,w16c(q)); o2=cmul(o2,w16c(2*q)); o3=cmul(o3,w16c(3*q)); }
        v[q]=o0; v[q+4]=o1; v[q+8]=o2; v[q+12]=o3;
    }
    C2 u4 = cmul(u2,u2);
    C2 u8 = cmul(u4,u4);
    C2 u12 = cmul(u8,u4);
    #pragma unroll
    for (int s = 0; s < 4; s++) {
        C2 a=v[4*s], b=v[4*s+1], c=v[4*s+2], d=v[4*s+3];
        C2 t0=cadd(a,c), t1=csub(a,c), t2=cadd(b,d), t3=mulni(csub(b,d));
        v[4*s]   = cadd(t0,t2);
        v[4*s+1] = cmul(cadd(t1,t3), u4);
        v[4*s+2] = cmul(csub(t0,t2), u8);
        v[4*s+3] = cmul(csub(t1,t3), u12);
    }
}

__device__ __forceinline__ void r16_inv(C2* v, C2 u1) {
    C2 u2 = cmul(u1,u1);
    C2 u4 = cmul(u2,u2);
    C2 u8 = cmul(u4,u4);
    C2 u12 = cmul(u8,u4);
    #pragma unroll
    for (int s = 0; s < 4; s++) {
        C2 a = v[4*s];
        C2 b = cmulc(v[4*s+1], u4);
        C2 c = cmulc(v[4*s+2], u8);
        C2 d = cmulc(v[4*s+3], u12);
        C2 p0=cadd(a,c), p1=csub(a,c), p2=cadd(b,d), p3=mulpi(csub(b,d));
        v[4*s]=cadd(p0,p2); v[4*s+1]=cadd(p1,p3); v[4*s+2]=csub(p0,p2); v[4*s+3]=csub(p1,p3);
    }
    C2 u3 = cmul(u2,u1);
    #pragma unroll
    for (int q = 0; q < 4; q++) {
        C2 a = v[q];
        C2 b = cmulc(v[q+4],  u1);
        C2 c = cmulc(v[q+8],  u2);
        C2 d = cmulc(v[q+12], u3);
        if (q) { b=cmulc(b,w16c(q)); c=cmulc(c,w16c(2*q)); d=cmulc(d,w16c(3*q)); }
        C2 p0=cadd(a,c), p1=csub(a,c), p2=cadd(b,d), p3=mulpi(csub(b,d));
        v[q]=cadd(p0,p2); v[q+4]=cadd(p1,p3); v[q+8]=csub(p0,p2); v[q+12]=csub(p1,p3);
    }
}

// pointwise packed-real product: A=Z[f], Braw=Z[N-f], Cv=Zk[f], Draw=Zk[N-f]
__device__ __forceinline__ void pw(C2 A, C2 Braw, C2 Cv, C2 Draw, C2& outF, C2& outNF) {
    const float s = 1.0f / (4.0f * (float)FFT_N);
    float br = Braw.x, bi = -Braw.y;
    float dr = Draw.x, di = -Draw.y;
    float apbr = A.x + br, apbi = A.y + bi;
    float ambr = A.x - br, ambi = A.y - bi;
    float cpdr = Cv.x + dr, cpdi = Cv.y + di;
    float cmdr = Cv.x - dr, cmdi = Cv.y - di;
    float Pr = apbr * cpdr - apbi * cpdi, Pi = apbr * cpdi + apbi * cpdr;
    float Qr = ambr * cmdr - ambi * cmdi, Qi = ambr * cmdi + ambi * cmdr;
    outF  = mkc((Pr + Qi) * s,  (Pi - Qr) * s);
    outNF = mkc((Pr - Qi) * s, -(Pi + Qr) * s);
}

// --------------------- shared-mem helpers / row passes ----------------------
__device__ __forceinline__ C2 lds(const float2* s, int i){ float2 t = s[SP2(i)]; return mkc(t.x,t.y); }
__device__ __forceinline__ void sts(float2* s, int i, C2 v){ s[SP2(i)] = make_float2(v.x,v.y); }

__device__ __forceinline__ void row_fwd(float2* s, int bf, int LM) {
    const int m = 1 << LM;
    const int r = bf & (m - 1);
    const int i0 = ((bf >> LM) << (LM + 4)) + r;
    C2 u1 = tw1k(r << (6 - LM));
    C2 v[16];
    #pragma unroll
    for (int j = 0; j < 16; j++) v[j] = lds(s, i0 + j*m);
    r16_fwd(v, u1);
    #pragma unroll
    for (int j = 0; j < 16; j++) sts(s, i0 + j*m, v[j]);
}
__device__ __forceinline__ void row_inv(float2* s, int bf, int LM) {
    const int m = 1 << LM;
    const int r = bf & (m - 1);
    const int i0 = ((bf >> LM) << (LM + 4)) + r;
    C2 u1 = tw1k(r << (6 - LM));
    C2 v[16];
    #pragma unroll
    for (int j = 0; j < 16; j++) v[j] = lds(s, i0 + j*m);
    r16_inv(v, u1);
    #pragma unroll
    for (int j = 0; j < 16; j++) sts(s, i0 + j*m, v[j]);
}

// ---------------- kA: x -> first 16-pt stage -> g_B (transposed) ------------
__global__ void __launch_bounds__(1024) kA(const float2* __restrict__ x2) {
    __shared__ __half2 tile[32][33];
    const int tx = threadIdx.x & 31, ty = threadIdx.x >> 5;
    const int b = blockIdx.z;
    const int pr0 = blockIdx.x * 32, n20 = blockIdx.y * 32;
    const float2* xb = x2 + (size_t)b * SEQ_L * NPAIR;
    const int n2 = n20 + ty;
    C2 v[16];
    #pragma unroll
    for (int j = 0; j < 8; j++) {
        float2 t = __ldg(&xb[(size_t)(j * 1024 + n2) * NPAIR + pr0 + tx]);
        v[j] = mkc(t.x, t.y);
    }
    r16_fwd_zfold(v, twN(n2));
    #pragma unroll
    for (int j = 0; j < 16; j++) {
        __syncthreads();
        tile[ty][tx] = __floats2half2_rn(v[j].x, v[j].y);
        __syncthreads();
        g_B[((size_t)(b * NPAIR + pr0 + ty) * 16 + j) * 1024 + n20 + tx] = tile[tx][ty];
    }
}

// ---------------- kAf: filt -> first stage -> g_kf (coalesced) --------------
__global__ void __launch_bounds__(1024) kAf(const float* __restrict__ filt) {
    const int n2 = threadIdx.x, pr = blockIdx.x;
    const float* k0 = filt + (size_t)(2 * pr) * SEQ_L;
    const float* k1 = k0 + SEQ_L;
    C2 v[16];
    #pragma unroll
    for (int j = 0; j < 8; j++) {
        int t = j * 1024 + n2;
        v[j] = mkc(k0[t], k1[t]);
    }
    r16_fwd_zfold(v, twN(n2));
    #pragma unroll
    for (int j = 0; j < 16; j++)
        g_kf[((size_t)pr * 16 + j) * 1024 + n2] = make_float2(v[j].x, v[j].y);
}

// ------- kBf: forward 1024-FFT of filter rows, [4,16,16] factorization ------
__global__ void __launch_bounds__(128) kBf() {
    __shared__ float2 s0[ROWLEN], s1[ROWLEN];
    const int t = threadIdx.x;
    const int pr = blockIdx.y, j0 = blockIdx.x * 2;
    float2* r0 = g_kf + ((size_t)pr * 16 + j0) * 1024;
    float2* r1 = r0 + 1024;
    float2* srow = (t >= 64) ? s1 : s0;
    float2* rX = (t >= 64) ? r1 : r0;
    const int bf = t & 63;
    // pass A: radix-4 m=256 fused with gmem load
    #pragma unroll
    for (int k = 0; k < 4; k++) {
        int r = bf + 64*k;
        float2 fa = rX[r], fb = rX[r+256], fc = rX[r+512], fd = rX[r+768];
        C2 a = mkc(fa.x,fa.y), b2 = mkc(fb.x,fb.y), c = mkc(fc.x,fc.y), d = mkc(fd.x,fd.y);
        C2 u = tw1k(r), u2 = cmul(u,u), u3 = cmul(u2,u);
        C2 t0=cadd(a,c), t1=csub(a,c), t2=cadd(b2,d), t3=mulni(csub(b2,d));
        sts(srow, r,     cadd(t0,t2));
        sts(srow, r+256, cmul(cadd(t1,t3), u));
        sts(srow, r+512, cmul(csub(t0,t2), u2));
        sts(srow, r+768, cmul(csub(t1,t3), u3));
    }
    __syncthreads();
    row_fwd(srow, bf, 4);
    __syncthreads();
    {   // final full 16-pt stage per chunk, coalesced gmem store
        C2 v[16];
        #pragma unroll
        for (int s = 0; s < 16; s++) v[s] = lds(srow, 16*bf + s);
        r16_fwd(v, mkc(1.f, 0.f));
        #pragma unroll
        for (int s = 0; s < 16; s++) rX[16*bf + s] = make_float2(v[s].x, v[s].y);
    }
}

// ---------------- kB: [4,16,16] row FFT + fused pointwise + inverse ---------
__global__ void __launch_bounds__(128, 8) kB() {
    __shared__ float2 s0[ROWLEN], s1[ROWLEN];
    const int t = threadIdx.x;
    const int b = blockIdx.x & 3, pi = blockIdx.x >> 2, pr = blockIdx.y;
    const int jA = c_jA[pi], jB = c_jB[pi];
    __half2* rA = g_B + ((size_t)(b * NPAIR + pr) * 16 + jA) * 1024;
    __half2* rB = g_B + ((size_t)(b * NPAIR + pr) * 16 + jB) * 1024;
    const float2* kfA = g_kf + ((size_t)pr * 16 + jA) * 1024;
    const float2* kfB = g_kf + ((size_t)pr * 16 + jB) * 1024;
    float2* srow = (t >= 64) ? s1 : s0;
    __half2* rX = (t >= 64) ? rB : rA;
    const float2* kfO = (t >= 64) ? kfB : kfA;
    const int bf = t & 63;

    // pass A fwd: radix-4 m=256 fused with coalesced gmem load
    #pragma unroll
    for (int k = 0; k < 4; k++) {
        int r = bf + 64*k;
        float2 fa = __half22float2(rX[r]);
        float2 fb = __half22float2(rX[r+256]);
        float2 fc = __half22float2(rX[r+512]);
        float2 fd = __half22float2(rX[r+768]);
        C2 a = mkc(fa.x,fa.y), b2 = mkc(fb.x,fb.y), c = mkc(fc.x,fc.y), d = mkc(fd.x,fd.y);
        C2 u = tw1k(r), u2 = cmul(u,u), u3 = cmul(u2,u);
        C2 t0=cadd(a,c), t1=csub(a,c), t2=cadd(b2,d), t3=mulni(csub(b2,d));
        sts(srow, r,     cadd(t0,t2));
        sts(srow, r+256, cmul(cadd(t1,t3), u));
        sts(srow, r+512, cmul(csub(t0,t2), u2));
        sts(srow, r+768, cmul(csub(t1,t3), u3));
    }
    __syncthreads();
    row_fwd(srow, bf, 4);
    __syncthreads();

    // phase C: per-chunk spectrum (full 16-pt stage in registers)
    C2 v[16];
    const int g = bf;
    #pragma unroll
    for (int s = 0; s < 16; s++) v[s] = lds(srow, 16*g + s);
    r16_fwd(v, mkc(1.f, 0.f));
    #pragma unroll
    for (int s = 0; s < 16; s++) sts(srow, 16*g + s, v[s]);  // publish spectrum
    __syncthreads();

    const bool special = (pi == 0) && (t < 64);   // row k1=0: frequency-indexed
    if (!special) {
        // one-sided pointwise: own position p pairs with partner position 1023-p
        const float2* prow = (pi == 0) ? s1 : ((t >= 64) ? s0 : s1);
        const float2* kfP  = (pi == 0) ? kfB : ((t >= 64) ? kfA : kfB);
        const int pg = 63 - g;
        #pragma unroll
        for (int s = 0; s < 16; s++) {
            C2 w = lds(prow, 16*pg + (15 - s));
            float2 uo = __ldg(&kfO[16*g + s]);        C2 co = mkc(uo.x, uo.y);
            float2 up = __ldg(&kfP[16*pg + 15 - s]);  C2 cp = mkc(up.x, up.y);
            C2 oF, oN;
            pw(v[s], w, co, cp, oF, oN);
            v[s] = oF;
        }
    }
    __syncthreads();   // all partner spectrum reads complete before writes

    if (!special) {
        r16_inv(v, mkc(1.f, 0.f));
        #pragma unroll
        for (int s = 0; s < 16; s++) sts(srow, 16*g + s, v[s]);
    } else {
        // row k1=0: k2 <-> (1024-k2) mod 1024, frequency-indexed positions
        for (int k2 = bf; k2 <= 512; k2 += 64) {
            int p  = p0f(k2);
            int q  = (1024 - k2) & 1023;
            int p2 = p0f(q);
            C2 A = lds(s0, p);
            float2 u = __ldg(&kfA[p]); C2 Cv = mkc(u.x, u.y);
            if (k2 == 0 || k2 == 512) {
                C2 o, dm; pw(A, A, Cv, Cv, o, dm); sts(s0, p, o);
            } else {
                C2 Bv = lds(s0, p2);
                float2 w2 = __ldg(&kfA[p2]); C2 Dv = mkc(w2.x, w2.y);
                C2 oF, oN; pw(A, Bv, Cv, Dv, oF, oN);
                sts(s0, p, oF); sts(s0, p2, oN);
            }
        }
    }
    __syncthreads();

    if (special) {  // finish chunk inverse for row 0
        #pragma unroll
        for (int s = 0; s < 16; s++) v[s] = lds(s0, 16*g + s);
        r16_inv(v, mkc(1.f, 0.f));
        #pragma unroll
        for (int s = 0; s < 16; s++) sts(s0, 16*g + s, v[s]);
    }
    __syncthreads();

    row_inv(srow, bf, 4);
    __syncthreads();

    // pass A inverse: conj twiddles + radix-4 fused with coalesced gmem store
    #pragma unroll
    for (int k = 0; k < 4; k++) {
        int r = bf + 64*k;
        C2 u = tw1k(r), u2 = cmul(u,u), u3 = cmul(u2,u);
        C2 a  = lds(srow, r);
        C2 b2 = cmulc(lds(srow, r+256), u);
        C2 c  = cmulc(lds(srow, r+512), u2);
        C2 d  = cmulc(lds(srow, r+768), u3);
        C2 p0=cadd(a,c), p1=csub(a,c), p2=cadd(b2,d), p3=mulpi(csub(b2,d));
        C2 o0=cadd(p0,p2), o1=cadd(p1,p3), o2=csub(p0,p2), o3=csub(p1,p3);
        rX[r]     = __floats2half2_rn(o0.x, o0.y);
        rX[r+256] = __floats2half2_rn(o1.x, o1.y);
        rX[r+512] = __floats2half2_rn(o2.x, o2.y);
        rX[r+768] = __floats2half2_rn(o3.x, o3.y);
    }
}

// ---------------- kC: 16-pt inverse stage -> y (transposed write) -----------
__global__ void __launch_bounds__(1024) kC(float2* __restrict__ y2) {
    __shared__ float2 tile[32][33];
    const int tx = threadIdx.x & 31, ty = threadIdx.x >> 5;
    const int b = blockIdx.z;
    const int pr0 = blockIdx.x * 32, n20 = blockIdx.y * 32;
    const int n2 = n20 + tx, pr = pr0 + ty;
    C2 v[16];
    #pragma unroll
    for (int j = 0; j < 16; j++) {
        float2 a = __half22float2(g_B[((size_t)(b * NPAIR + pr) * 16 + j) * 1024 + n2]);
        v[j] = mkc(a.x, a.y);
    }
    r16_inv(v, twN(n2));
    float2* yb = y2 + (size_t)b * SEQ_L * NPAIR;
    #pragma unroll
    for (int j = 0; j < 8; j++) {
        __syncthreads();
        tile[ty][tx] = make_float2(v[j].x, v[j].y);
        __syncthreads();
        yb[(size_t)(j * 1024 + n20 + ty) * NPAIR + pr0 + tx] = tile[tx][ty];
    }
}

// ------------------------------ launch --------------------------------------
extern "C" void kernel_launch(void* const* d_in, const int* in_sizes, int n_in,
                              void* d_out, int out_size) {
    const float* x    = (const float*)d_in[0];
    const float* filt = (const float*)d_in[1];
    if (n_in >= 2 && in_sizes[0] == 2 * NPAIR * SEQ_L &&
        in_sizes[1] == NBATCH * SEQ_L * 2 * NPAIR) {
        const float* t = x; x = filt; filt = t;
    }
    float* out = (float*)d_out;

    kAf<<<NPAIR, 1024>>>(filt);
    kBf<<<dim3(8, NPAIR), 128>>>();
    kA<<<dim3(16, 32, NBATCH), 1024>>>((const float2*)x);
    kB<<<dim3(32, NPAIR), 128>>>();
    kC<<<dim3(16, 32, NBATCH), 1024>>>((float2*)out);
}

// round 12
// speedup vs baseline: 1.5454x; 1.5454x over previous
#include <cuda_runtime.h>
#include <cuda_fp16.h>
#include <math.h>

#define SEQ_L  8192
#define NPAIR  512
#define NBATCH 4
#define FFT_N  16384
#define ROWLEN 1088                 // 1024 + pad
#define SP2(i) ((i) + ((i) >> 4))

// -------- device globals (no cudaMalloc allowed) ----------------------------
__device__ __half2 g_B[(size_t)NBATCH * NPAIR * 16 * 1024];   // 134 MB staging
__device__ float2  g_kf[(size_t)NPAIR * 16 * 1024];           // 67 MB filter table
__constant__ int c_jA[8] = {0, 1, 4, 5, 6, 7, 8, 9};
__constant__ int c_jB[8] = {2, 3, 15, 14, 13, 12, 11, 10};

// ----------------------------- complex helpers ------------------------------
struct C2 { float x, y; };
__device__ __forceinline__ C2 mkc(float a, float b){ C2 r; r.x=a; r.y=b; return r; }
__device__ __forceinline__ C2 cadd(C2 a, C2 b){ return mkc(a.x+b.x, a.y+b.y); }
__device__ __forceinline__ C2 csub(C2 a, C2 b){ return mkc(a.x-b.x, a.y-b.y); }
__device__ __forceinline__ C2 cmul(C2 a, C2 b){ return mkc(a.x*b.x - a.y*b.y, a.x*b.y + a.y*b.x); }
__device__ __forceinline__ C2 cmulc(C2 a, C2 b){ return mkc(a.x*b.x + a.y*b.y, a.y*b.x - a.x*b.y); }
__device__ __forceinline__ C2 mulni(C2 a){ return mkc(a.y, -a.x); }
__device__ __forceinline__ C2 mulpi(C2 a){ return mkc(-a.y, a.x); }

__device__ __forceinline__ C2 w16c(int n) {
    const float C[10] = {1.f, 0.92387953f, 0.70710678f, 0.38268343f, 0.f,
                         -0.38268343f, -0.70710678f, -0.92387953f, -1.f, -0.92387953f};
    const float S[10] = {0.f, -0.38268343f, -0.70710678f, -0.92387953f, -1.f,
                         -0.92387953f, -0.70710678f, -0.38268343f, 0.f, 0.38268343f};
    return mkc(C[n], S[n]);
}
__device__ __forceinline__ C2 twN(int j) {   // W_16384^j
    float sv, cv; sincospif(-(float)j * (1.0f/8192.0f), &sv, &cv); return mkc(cv, sv);
}
__device__ __forceinline__ C2 tw1k(int j) {  // W_1024^j
    float sv, cv; sincospif(-(float)j * (1.0f/512.0f), &sv, &cv); return mkc(cv, sv);
}
// digit-reverse base-4 of 10-bit index (5 digits). Self-inverse.
__device__ __forceinline__ int drev10(int p) {
    unsigned r = __brev((unsigned)p) >> 22;
    return (int)(((r & 0x155u) << 1) | ((r & 0x2AAu) >> 1));
}

// ---------------- register radix-16 (two fused radix-4 layers) --------------
__device__ __forceinline__ void r16_fwd(C2* v, C2 u1) {
    C2 u2 = cmul(u1,u1);
    C2 u3 = cmul(u2,u1);
    #pragma unroll
    for (int q = 0; q < 4; q++) {
        C2 a=v[q], b=v[q+4], c=v[q+8], d=v[q+12];
        C2 t0=cadd(a,c), t1=csub(a,c), t2=cadd(b,d), t3=mulni(csub(b,d));
        v[q] = cadd(t0,t2);
        C2 o1 = cmul(cadd(t1,t3), u1);
        C2 o2 = cmul(csub(t0,t2), u2);
        C2 o3 = cmul(csub(t1,t3), u3);
        if (q) { o1=cmul(o1,w16c(q)); o2=cmul(o2,w16c(2*q)); o3=cmul(o3,w16c(3*q)); }
        v[q+4]=o1; v[q+8]=o2; v[q+12]=o3;
    }
    C2 u4 = cmul(u2,u2);
    C2 u8 = cmul(u4,u4);
    C2 u12 = cmul(u8,u4);
    #pragma unroll
    for (int s = 0; s < 4; s++) {
        C2 a=v[4*s], b=v[4*s+1], c=v[4*s+2], d=v[4*s+3];
        C2 t0=cadd(a,c), t1=csub(a,c), t2=cadd(b,d), t3=mulni(csub(b,d));
        v[4*s]   = cadd(t0,t2);
        v[4*s+1] = cmul(cadd(t1,t3), u4);
        v[4*s+2] = cmul(csub(t0,t2), u8);
        v[4*s+3] = cmul(csub(t1,t3), u12);
    }
}

__device__ __forceinline__ void r16_fwd_zfold(C2* v, C2 u1) {
    C2 u2 = cmul(u1,u1);
    C2 u3 = cmul(u2,u1);
    #pragma unroll
    for (int q = 0; q < 4; q++) {
        C2 a=v[q], b=v[q+4];
        C2 nb = mulni(b);
        C2 o0 = cadd(a,b);
        C2 o1 = cmul(cadd(a,nb), u1);
        C2 o2 = cmul(csub(a,b), u2);
        C2 o3 = cmul(csub(a,nb), u3);
        if (q) { o1=cmul(o1,w16c(q)); o2=cmul(o2,w16c(2*q)); o3=cmul(o3,w16c(3*q)); }
        v[q]=o0; v[q+4]=o1; v[q+8]=o2; v[q+12]=o3;
    }
    C2 u4 = cmul(u2,u2);
    C2 u8 = cmul(u4,u4);
    C2 u12 = cmul(u8,u4);
    #pragma unroll
    for (int s = 0; s < 4; s++) {
        C2 a=v[4*s], b=v[4*s+1], c=v[4*s+2], d=v[4*s+3];
        C2 t0=cadd(a,c), t1=csub(a,c), t2=cadd(b,d), t3=mulni(csub(b,d));
        v[4*s]   = cadd(t0,t2);
        v[4*s+1] = cmul(cadd(t1,t3), u4);
        v[4*s+2] = cmul(csub(t0,t2), u8);
        v[4*s+3] = cmul(csub(t1,t3), u12);
    }
}

__device__ __forceinline__ void r16_inv(C2* v, C2 u1) {
    C2 u2 = cmul(u1,u1);
    C2 u4 = cmul(u2,u2);
    C2 u8 = cmul(u4,u4);
    C2 u12 = cmul(u8,u4);
    #pragma unroll
    for (int s = 0; s < 4; s++) {
        C2 a = v[4*s];
        C2 b = cmulc(v[4*s+1], u4);
        C2 c = cmulc(v[4*s+2], u8);
        C2 d = cmulc(v[4*s+3], u12);
        C2 p0=cadd(a,c), p1=csub(a,c), p2=cadd(b,d), p3=mulpi(csub(b,d));
        v[4*s]=cadd(p0,p2); v[4*s+1]=cadd(p1,p3); v[4*s+2]=csub(p0,p2); v[4*s+3]=csub(p1,p3);
    }
    C2 u3 = cmul(u2,u1);
    #pragma unroll
    for (int q = 0; q < 4; q++) {
        C2 a = v[q];
        C2 b = cmulc(v[q+4],  u1);
        C2 c = cmulc(v[q+8],  u2);
        C2 d = cmulc(v[q+12], u3);
        if (q) { b=cmulc(b,w16c(q)); c=cmulc(c,w16c(2*q)); d=cmulc(d,w16c(3*q)); }
        C2 p0=cadd(a,c), p1=csub(a,c), p2=cadd(b,d), p3=mulpi(csub(b,d));
        v[q]=cadd(p0,p2); v[q+4]=cadd(p1,p3); v[q+8]=csub(p0,p2); v[q+12]=csub(p1,p3);
    }
}

__device__ __forceinline__ void fwd4(C2& a, C2& b, C2& c, C2& d) {
    C2 t0=cadd(a,c), t1=csub(a,c), t2=cadd(b,d), t3=mulni(csub(b,d));
    a=cadd(t0,t2); b=cadd(t1,t3); c=csub(t0,t2); d=csub(t1,t3);
}
__device__ __forceinline__ void inv4(C2& a, C2& b, C2& c, C2& d) {
    C2 p0=cadd(a,c), p1=csub(a,c), p2=cadd(b,d), p3=mulpi(csub(b,d));
    a=cadd(p0,p2); b=cadd(p1,p3); c=csub(p0,p2); d=csub(p1,p3);
}

// pointwise packed-real product: A=Z[f], Braw=Z[N-f], Cv=Zk[f], Draw=Zk[N-f]
__device__ __forceinline__ void pw(C2 A, C2 Braw, C2 Cv, C2 Draw, C2& outF, C2& outNF) {
    const float s = 1.0f / (4.0f * (float)FFT_N);
    float br = Braw.x, bi = -Braw.y;
    float dr = Draw.x, di = -Draw.y;
    float apbr = A.x + br, apbi = A.y + bi;
    float ambr = A.x - br, ambi = A.y - bi;
    float cpdr = Cv.x + dr, cpdi = Cv.y + di;
    float cmdr = Cv.x - dr, cmdi = Cv.y - di;
    float Pr = apbr * cpdr - apbi * cpdi, Pi = apbr * cpdi + apbi * cpdr;
    float Qr = ambr * cmdr - ambi * cmdi, Qi = ambr * cmdi + ambi * cmdr;
    outF  = mkc((Pr + Qi) * s,  (Pi - Qr) * s);
    outNF = mkc((Pr - Qi) * s, -(Pi + Qr) * s);
}

// --------------------- 1024-point row passes in smem ------------------------
__device__ __forceinline__ C2 lds(const float2* s, int i){ float2 t = s[SP2(i)]; return mkc(t.x,t.y); }
__device__ __forceinline__ void sts(float2* s, int i, C2 v){ s[SP2(i)] = make_float2(v.x,v.y); }

__device__ __forceinline__ void row_fwd(float2* s, int bf, int LM) {
    const int m = 1 << LM;
    const int r = bf & (m - 1);
    const int i0 = ((bf >> LM) << (LM + 4)) + r;
    C2 u1 = tw1k(r << (6 - LM));
    C2 v[16];
    #pragma unroll
    for (int j = 0; j < 16; j++) v[j] = lds(s, i0 + j*m);
    r16_fwd(v, u1);
    #pragma unroll
    for (int j = 0; j < 16; j++) sts(s, i0 + j*m, v[j]);
}
__device__ __forceinline__ void row_inv(float2* s, int bf, int LM) {
    const int m = 1 << LM;
    const int r = bf & (m - 1);
    const int i0 = ((bf >> LM) << (LM + 4)) + r;
    C2 u1 = tw1k(r << (6 - LM));
    C2 v[16];
    #pragma unroll
    for (int j = 0; j < 16; j++) v[j] = lds(s, i0 + j*m);
    r16_inv(v, u1);
    #pragma unroll
    for (int j = 0; j < 16; j++) sts(s, i0 + j*m, v[j]);
}

// ---------------- kA: x -> first 16-pt stage -> g_B (transposed) ------------
__global__ void __launch_bounds__(1024) kA(const float2* __restrict__ x2) {
    __shared__ __half2 tile[32][33];
    const int tx = threadIdx.x & 31, ty = threadIdx.x >> 5;
    const int b = blockIdx.z;
    const int pr0 = blockIdx.x * 32, n20 = blockIdx.y * 32;
    const float2* xb = x2 + (size_t)b * SEQ_L * NPAIR;
    const int n2 = n20 + ty;
    C2 v[16];
    #pragma unroll
    for (int j = 0; j < 8; j++) {
        float2 t = __ldg(&xb[(size_t)(j * 1024 + n2) * NPAIR + pr0 + tx]);
        v[j] = mkc(t.x, t.y);
    }
    r16_fwd_zfold(v, twN(n2));
    #pragma unroll
    for (int j = 0; j < 16; j++) {
        __syncthreads();
        tile[ty][tx] = __floats2half2_rn(v[j].x, v[j].y);
        __syncthreads();
        g_B[((size_t)(b * NPAIR + pr0 + ty) * 16 + j) * 1024 + n20 + tx] = tile[tx][ty];
    }
}

// ---------------- kAf: filt -> first stage -> g_kf (coalesced) --------------
__global__ void __launch_bounds__(1024) kAf(const float* __restrict__ filt) {
    const int n2 = threadIdx.x, pr = blockIdx.x;
    const float* k0 = filt + (size_t)(2 * pr) * SEQ_L;
    const float* k1 = k0 + SEQ_L;
    C2 v[16];
    #pragma unroll
    for (int j = 0; j < 8; j++) {
        int t = j * 1024 + n2;
        v[j] = mkc(k0[t], k1[t]);
    }
    r16_fwd_zfold(v, twN(n2));
    #pragma unroll
    for (int j = 0; j < 16; j++)
        g_kf[((size_t)pr * 16 + j) * 1024 + n2] = make_float2(v[j].x, v[j].y);
}

// ---------------- kBf: forward 1024-FFT of filter rows (in place) -----------
__global__ void __launch_bounds__(128) kBf() {
    __shared__ float2 s0[ROWLEN], s1[ROWLEN];
    const int t = threadIdx.x;
    const int pr = blockIdx.y, j0 = blockIdx.x * 2;
    float2* r0 = g_kf + ((size_t)pr * 16 + j0) * 1024;
    float2* r1 = r0 + 1024;
    for (int i = t; i < 1024; i += 128) { s0[SP2(i)] = r0[i]; s1[SP2(i)] = r1[i]; }
    __syncthreads();
    float2* srow = (t >= 64) ? s1 : s0;
    const int bf = t & 63;
    row_fwd(srow, bf, 6); __syncthreads();
    row_fwd(srow, bf, 2); __syncthreads();
    for (int idx = t; idx < 512; idx += 128) {
        float2* s = (idx & 256) ? s1 : s0;
        float2* r = (idx & 256) ? r1 : r0;
        int g = idx & 255;
        C2 a = lds(s,4*g), b = lds(s,4*g+1), c = lds(s,4*g+2), d = lds(s,4*g+3);
        fwd4(a, b, c, d);
        r[4*g]   = make_float2(a.x, a.y);
        r[4*g+1] = make_float2(b.x, b.y);
        r[4*g+2] = make_float2(c.x, c.y);
        r[4*g+3] = make_float2(d.x, d.y);
    }
}

// ---------------- kB: row FFT + pointwise + row inverse ---------------------
__global__ void __launch_bounds__(128, 8) kB() {
    __shared__ float2 s0[ROWLEN], s1[ROWLEN];
    const int t = threadIdx.x;
    const int b = blockIdx.x & 3, pi = blockIdx.x >> 2, pr = blockIdx.y;
    const int jA = c_jA[pi], jB = c_jB[pi];
    __half2* rA = g_B + ((size_t)(b * NPAIR + pr) * 16 + jA) * 1024;
    __half2* rB = g_B + ((size_t)(b * NPAIR + pr) * 16 + jB) * 1024;
    const float2* kfA = g_kf + ((size_t)pr * 16 + jA) * 1024;
    const float2* kfB = g_kf + ((size_t)pr * 16 + jB) * 1024;
    // vectorized load: 2 half2 per 8B transaction
    const float2* rA2 = (const float2*)rA;
    const float2* rB2 = (const float2*)rB;
    for (int i = t; i < 512; i += 128) {
        float2 pa = rA2[i];
        __half2 h0 = *(__half2*)&pa.x, h1 = *(__half2*)&pa.y;
        s0[SP2(2*i)]   = __half22float2(h0);
        s0[SP2(2*i+1)] = __half22float2(h1);
        float2 pb = rB2[i];
        __half2 g0 = *(__half2*)&pb.x, g1 = *(__half2*)&pb.y;
        s1[SP2(2*i)]   = __half22float2(g0);
        s1[SP2(2*i+1)] = __half22float2(g1);
    }
    __syncthreads();
    float2* srow = (t >= 64) ? s1 : s0;
    const int bf = t & 63;
    row_fwd(srow, bf, 6); __syncthreads();
    row_fwd(srow, bf, 2); __syncthreads();

    if (pi) {
        // cross pair: row A pos p  <->  row B pos 1023-p
        #pragma unroll
        for (int gi = 0; gi < 2; gi++) {
            int g = t + gi * 128, g2 = 255 - g;
            C2 a[4], bb[4], ka[4], kb[4];
            #pragma unroll
            for (int s = 0; s < 4; s++) a[s] = lds(s0, 4*g + s);
            fwd4(a[0], a[1], a[2], a[3]);
            #pragma unroll
            for (int s = 0; s < 4; s++) bb[s] = lds(s1, 4*g2 + s);
            fwd4(bb[0], bb[1], bb[2], bb[3]);
            #pragma unroll
            for (int s = 0; s < 4; s++) {
                float2 u = __ldg(&kfA[4*g + s]);  ka[s] = mkc(u.x, u.y);
                float2 w = __ldg(&kfB[4*g2 + s]); kb[s] = mkc(w.x, w.y);
            }
            #pragma unroll
            for (int s = 0; s < 4; s++) pw(a[s], bb[3-s], ka[s], kb[3-s], a[s], bb[3-s]);
            inv4(a[0], a[1], a[2], a[3]);
            inv4(bb[0], bb[1], bb[2], bb[3]);
            #pragma unroll
            for (int s = 0; s < 4; s++) { sts(s0, 4*g + s, a[s]); sts(s1, 4*g2 + s, bb[s]); }
        }
    } else {
        // row s1 = k1=8: self-mirrored, p <-> 1023-p within the row
        {
            int g = t, g2 = 255 - t;
            C2 a[4], bb[4], ka[4], kb[4];
            #pragma unroll
            for (int s = 0; s < 4; s++) a[s] = lds(s1, 4*g + s);
            fwd4(a[0], a[1], a[2], a[3]);
            #pragma unroll
            for (int s = 0; s < 4; s++) bb[s] = lds(s1, 4*g2 + s);
            fwd4(bb[0], bb[1], bb[2], bb[3]);
            #pragma unroll
            for (int s = 0; s < 4; s++) {
                float2 u = __ldg(&kfB[4*g + s]);  ka[s] = mkc(u.x, u.y);
                float2 w = __ldg(&kfB[4*g2 + s]); kb[s] = mkc(w.x, w.y);
            }
            #pragma unroll
            for (int s = 0; s < 4; s++) pw(a[s], bb[3-s], ka[s], kb[3-s], a[s], bb[3-s]);
            inv4(a[0], a[1], a[2], a[3]);
            inv4(bb[0], bb[1], bb[2], bb[3]);
            #pragma unroll
            for (int s = 0; s < 4; s++) { sts(s1, 4*g + s, a[s]); sts(s1, 4*g2 + s, bb[s]); }
        }
        // row s0 = k1=0: complete forward, frequency-indexed pairing, inverse
        for (int g = t; g < 256; g += 128) {
            C2 a = lds(s0,4*g), b2 = lds(s0,4*g+1), c = lds(s0,4*g+2), d = lds(s0,4*g+3);
            fwd4(a, b2, c, d);
            sts(s0,4*g,a); sts(s0,4*g+1,b2); sts(s0,4*g+2,c); sts(s0,4*g+3,d);
        }
        __syncthreads();
        for (int k2 = t; k2 <= 512; k2 += 128) {
            int p  = drev10(k2);
            int p2 = drev10((1024 - k2) & 1023);
            C2 A = lds(s0, p);
            float2 u = __ldg(&kfA[p]); C2 Cv = mkc(u.x, u.y);
            if (k2 == 0 || k2 == 512) {
                C2 o, dm; pw(A, A, Cv, Cv, o, dm); sts(s0, p, o);
            } else {
                C2 Bv = lds(s0, p2);
                float2 w = __ldg(&kfA[p2]); C2 Dv = mkc(w.x, w.y);
                C2 oF, oN; pw(A, Bv, Cv, Dv, oF, oN);
                sts(s0, p, oF); sts(s0, p2, oN);
            }
        }
        __syncthreads();
        for (int g = t; g < 256; g += 128) {
            C2 a = lds(s0,4*g), b2 = lds(s0,4*g+1), c = lds(s0,4*g+2), d = lds(s0,4*g+3);
            inv4(a, b2, c, d);
            sts(s0,4*g,a); sts(s0,4*g+1,b2); sts(s0,4*g+2,c); sts(s0,4*g+3,d);
        }
    }
    __syncthreads();
    row_inv(srow, bf, 2); __syncthreads();
    row_inv(srow, bf, 6); __syncthreads();
    // vectorized store: 2 half2 per 8B transaction
    float2* wA2 = (float2*)rA;
    float2* wB2 = (float2*)rB;
    for (int i = t; i < 512; i += 128) {
        float2 a0 = s0[SP2(2*i)], a1 = s0[SP2(2*i+1)];
        float2 oa;
        *(__half2*)&oa.x = __floats2half2_rn(a0.x, a0.y);
        *(__half2*)&oa.y = __floats2half2_rn(a1.x, a1.y);
        wA2[i] = oa;
        float2 b0 = s1[SP2(2*i)], b1 = s1[SP2(2*i+1)];
        float2 ob;
        *(__half2*)&ob.x = __floats2half2_rn(b0.x, b0.y);
        *(__half2*)&ob.y = __floats2half2_rn(b1.x, b1.y);
        wB2[i] = ob;
    }
}

// ---------------- kC: 16-pt inverse stage -> y (transposed write) -----------
__global__ void __launch_bounds__(1024) kC(float2* __restrict__ y2) {
    __shared__ float2 tile[32][33];
    const int tx = threadIdx.x & 31, ty = threadIdx.x >> 5;
    const int b = blockIdx.z;
    const int pr0 = blockIdx.x * 32, n20 = blockIdx.y * 32;
    const int n2 = n20 + tx, pr = pr0 + ty;
    C2 v[16];
    #pragma unroll
    for (int j = 0; j < 16; j++) {
        float2 a = __half22float2(g_B[((size_t)(b * NPAIR + pr) * 16 + j) * 1024 + n2]);
        v[j] = mkc(a.x, a.y);
    }
    r16_inv(v, twN(n2));
    float2* yb = y2 + (size_t)b * SEQ_L * NPAIR;
    #pragma unroll
    for (int j = 0; j < 8; j++) {
        __syncthreads();
        tile[ty][tx] = make_float2(v[j].x, v[j].y);
        __syncthreads();
        yb[(size_t)(j * 1024 + n20 + ty) * NPAIR + pr0 + tx] = tile[tx][ty];
    }
}

// ------------------------------ launch --------------------------------------
extern "C" void kernel_launch(void* const* d_in, const int* in_sizes, int n_in,
                              void* d_out, int out_size) {
    const float* x    = (const float*)d_in[0];
    const float* filt = (const float*)d_in[1];
    if (n_in >= 2 && in_sizes[0] == 2 * NPAIR * SEQ_L &&
        in_sizes[1] == NBATCH * SEQ_L * 2 * NPAIR) {
        const float* t = x; x = filt; filt = t;
    }
    float* out = (float*)d_out;

    kAf<<<NPAIR, 1024>>>(filt);
    kBf<<<dim3(8, NPAIR), 128>>>();
    kA<<<dim3(16, 32, NBATCH), 1024>>>((const float2*)x);
    kB<<<dim3(32, NPAIR), 128>>>();
    kC<<<dim3(16, 32, NBATCH), 1024>>>((float2*)out);
}

// round 13
// speedup vs baseline: 1.6210x; 1.0489x over previous
#include <cuda_runtime.h>
#include <cuda_fp16.h>
#include <math.h>

#define SEQ_L  8192
#define NPAIR  512
#define NBATCH 4
#define FFT_N  16384
#define ROWLEN 1088                 // 1024 + pad
#define SP2(i) ((i) + ((i) >> 4))

// -------- device globals (no cudaMalloc allowed) ----------------------------
__device__ __half2 g_B[(size_t)NBATCH * NPAIR * 16 * 1024];   // 134 MB staging
__device__ __half2 g_kf[(size_t)NPAIR * 16 * 1024];           // 33.5 MB final filter table
__device__ float2  g_kft[(size_t)NPAIR * 16 * 1024];          // 67 MB fp32 intermediate
__constant__ int c_jA[8] = {0, 1, 4, 5, 6, 7, 8, 9};
__constant__ int c_jB[8] = {2, 3, 15, 14, 13, 12, 11, 10};

// ----------------------------- complex helpers ------------------------------
struct C2 { float x, y; };
__device__ __forceinline__ C2 mkc(float a, float b){ C2 r; r.x=a; r.y=b; return r; }
__device__ __forceinline__ C2 cadd(C2 a, C2 b){ return mkc(a.x+b.x, a.y+b.y); }
__device__ __forceinline__ C2 csub(C2 a, C2 b){ return mkc(a.x-b.x, a.y-b.y); }
__device__ __forceinline__ C2 cmul(C2 a, C2 b){ return mkc(a.x*b.x - a.y*b.y, a.x*b.y + a.y*b.x); }
__device__ __forceinline__ C2 cmulc(C2 a, C2 b){ return mkc(a.x*b.x + a.y*b.y, a.y*b.x - a.x*b.y); }
__device__ __forceinline__ C2 mulni(C2 a){ return mkc(a.y, -a.x); }
__device__ __forceinline__ C2 mulpi(C2 a){ return mkc(-a.y, a.x); }

__device__ __forceinline__ C2 w16c(int n) {
    const float C[10] = {1.f, 0.92387953f, 0.70710678f, 0.38268343f, 0.f,
                         -0.38268343f, -0.70710678f, -0.92387953f, -1.f, -0.92387953f};
    const float S[10] = {0.f, -0.38268343f, -0.70710678f, -0.92387953f, -1.f,
                         -0.92387953f, -0.70710678f, -0.38268343f, 0.f, 0.38268343f};
    return mkc(C[n], S[n]);
}
__device__ __forceinline__ C2 twN(int j) {   // W_16384^j
    float sv, cv; sincospif(-(float)j * (1.0f/8192.0f), &sv, &cv); return mkc(cv, sv);
}
__device__ __forceinline__ C2 tw1k(int j) {  // W_1024^j
    float sv, cv; sincospif(-(float)j * (1.0f/512.0f), &sv, &cv); return mkc(cv, sv);
}
// digit-reverse base-4 of 10-bit index (5 digits). Self-inverse.
__device__ __forceinline__ int drev10(int p) {
    unsigned r = __brev((unsigned)p) >> 22;
    return (int)(((r & 0x155u) << 1) | ((r & 0x2AAu) >> 1));
}
// half2 table load -> C2
__device__ __forceinline__ C2 ldk(const __half2* k, int i) {
    float2 t = __half22float2(__ldg(&k[i]));
    return mkc(t.x, t.y);
}

// ---------------- register radix-16 (two fused radix-4 layers) --------------
__device__ __forceinline__ void r16_fwd(C2* v, C2 u1) {
    C2 u2 = cmul(u1,u1);
    C2 u3 = cmul(u2,u1);
    #pragma unroll
    for (int q = 0; q < 4; q++) {
        C2 a=v[q], b=v[q+4], c=v[q+8], d=v[q+12];
        C2 t0=cadd(a,c), t1=csub(a,c), t2=cadd(b,d), t3=mulni(csub(b,d));
        v[q] = cadd(t0,t2);
        C2 o1 = cmul(cadd(t1,t3), u1);
        C2 o2 = cmul(csub(t0,t2), u2);
        C2 o3 = cmul(csub(t1,t3), u3);
        if (q) { o1=cmul(o1,w16c(q)); o2=cmul(o2,w16c(2*q)); o3=cmul(o3,w16c(3*q)); }
        v[q+4]=o1; v[q+8]=o2; v[q+12]=o3;
    }
    C2 u4 = cmul(u2,u2);
    C2 u8 = cmul(u4,u4);
    C2 u12 = cmul(u8,u4);
    #pragma unroll
    for (int s = 0; s < 4; s++) {
        C2 a=v[4*s], b=v[4*s+1], c=v[4*s+2], d=v[4*s+3];
        C2 t0=cadd(a,c), t1=csub(a,c), t2=cadd(b,d), t3=mulni(csub(b,d));
        v[4*s]   = cadd(t0,t2);
        v[4*s+1] = cmul(cadd(t1,t3), u4);
        v[4*s+2] = cmul(csub(t0,t2), u8);
        v[4*s+3] = cmul(csub(t1,t3), u12);
    }
}

__device__ __forceinline__ void r16_fwd_zfold(C2* v, C2 u1) {
    C2 u2 = cmul(u1,u1);
    C2 u3 = cmul(u2,u1);
    #pragma unroll
    for (int q = 0; q < 4; q++) {
        C2 a=v[q], b=v[q+4];
        C2 nb = mulni(b);
        C2 o0 = cadd(a,b);
        C2 o1 = cmul(cadd(a,nb), u1);
        C2 o2 = cmul(csub(a,b), u2);
        C2 o3 = cmul(csub(a,nb), u3);
        if (q) { o1=cmul(o1,w16c(q)); o2=cmul(o2,w16c(2*q)); o3=cmul(o3,w16c(3*q)); }
        v[q]=o0; v[q+4]=o1; v[q+8]=o2; v[q+12]=o3;
    }
    C2 u4 = cmul(u2,u2);
    C2 u8 = cmul(u4,u4);
    C2 u12 = cmul(u8,u4);
    #pragma unroll
    for (int s = 0; s < 4; s++) {
        C2 a=v[4*s], b=v[4*s+1], c=v[4*s+2], d=v[4*s+3];
        C2 t0=cadd(a,c), t1=csub(a,c), t2=cadd(b,d), t3=mulni(csub(b,d));
        v[4*s]   = cadd(t0,t2);
        v[4*s+1] = cmul(cadd(t1,t3), u4);
        v[4*s+2] = cmul(csub(t0,t2), u8);
        v[4*s+3] = cmul(csub(t1,t3), u12);
    }
}

__device__ __forceinline__ void r16_inv(C2* v, C2 u1) {
    C2 u2 = cmul(u1,u1);
    C2 u4 = cmul(u2,u2);
    C2 u8 = cmul(u4,u4);
    C2 u12 = cmul(u8,u4);
    #pragma unroll
    for (int s = 0; s < 4; s++) {
        C2 a = v[4*s];
        C2 b = cmulc(v[4*s+1], u4);
        C2 c = cmulc(v[4*s+2], u8);
        C2 d = cmulc(v[4*s+3], u12);
        C2 p0=cadd(a,c), p1=csub(a,c), p2=cadd(b,d), p3=mulpi(csub(b,d));
        v[4*s]=cadd(p0,p2); v[4*s+1]=cadd(p1,p3); v[4*s+2]=csub(p0,p2); v[4*s+3]=csub(p1,p3);
    }
    C2 u3 = cmul(u2,u1);
    #pragma unroll
    for (int q = 0; q < 4; q++) {
        C2 a = v[q];
        C2 b = cmulc(v[q+4],  u1);
        C2 c = cmulc(v[q+8],  u2);
        C2 d = cmulc(v[q+12], u3);
        if (q) { b=cmulc(b,w16c(q)); c=cmulc(c,w16c(2*q)); d=cmulc(d,w16c(3*q)); }
        C2 p0=cadd(a,c), p1=csub(a,c), p2=cadd(b,d), p3=mulpi(csub(b,d));
        v[q]=cadd(p0,p2); v[q+4]=cadd(p1,p3); v[q+8]=csub(p0,p2); v[q+12]=csub(p1,p3);
    }
}

__device__ __forceinline__ void fwd4(C2& a, C2& b, C2& c, C2& d) {
    C2 t0=cadd(a,c), t1=csub(a,c), t2=cadd(b,d), t3=mulni(csub(b,d));
    a=cadd(t0,t2); b=cadd(t1,t3); c=csub(t0,t2); d=csub(t1,t3);
}
__device__ __forceinline__ void inv4(C2& a, C2& b, C2& c, C2& d) {
    C2 p0=cadd(a,c), p1=csub(a,c), p2=cadd(b,d), p3=mulpi(csub(b,d));
    a=cadd(p0,p2); b=cadd(p1,p3); c=csub(p0,p2); d=csub(p1,p3);
}

// pointwise packed-real product: A=Z[f], Braw=Z[N-f], Cv=Zk[f], Draw=Zk[N-f]
__device__ __forceinline__ void pw(C2 A, C2 Braw, C2 Cv, C2 Draw, C2& outF, C2& outNF) {
    const float s = 1.0f / (4.0f * (float)FFT_N);
    float br = Braw.x, bi = -Braw.y;
    float dr = Draw.x, di = -Draw.y;
    float apbr = A.x + br, apbi = A.y + bi;
    float ambr = A.x - br, ambi = A.y - bi;
    float cpdr = Cv.x + dr, cpdi = Cv.y + di;
    float cmdr = Cv.x - dr, cmdi = Cv.y - di;
    float Pr = apbr * cpdr - apbi * cpdi, Pi = apbr * cpdi + apbi * cpdr;
    float Qr = ambr * cmdr - ambi * cmdi, Qi = ambr * cmdi + ambi * cmdr;
    outF  = mkc((Pr + Qi) * s,  (Pi - Qr) * s);
    outNF = mkc((Pr - Qi) * s, -(Pi + Qr) * s);
}

// --------------------- 1024-point row passes in smem ------------------------
__device__ __forceinline__ C2 lds(const float2* s, int i){ float2 t = s[SP2(i)]; return mkc(t.x,t.y); }
__device__ __forceinline__ void sts(float2* s, int i, C2 v){ s[SP2(i)] = make_float2(v.x,v.y); }

__device__ __forceinline__ void row_fwd(float2* s, int bf, int LM) {
    const int m = 1 << LM;
    const int r = bf & (m - 1);
    const int i0 = ((bf >> LM) << (LM + 4)) + r;
    C2 u1 = tw1k(r << (6 - LM));
    C2 v[16];
    #pragma unroll
    for (int j = 0; j < 16; j++) v[j] = lds(s, i0 + j*m);
    r16_fwd(v, u1);
    #pragma unroll
    for (int j = 0; j < 16; j++) sts(s, i0 + j*m, v[j]);
}
__device__ __forceinline__ void row_inv(float2* s, int bf, int LM) {
    const int m = 1 << LM;
    const int r = bf & (m - 1);
    const int i0 = ((bf >> LM) << (LM + 4)) + r;
    C2 u1 = tw1k(r << (6 - LM));
    C2 v[16];
    #pragma unroll
    for (int j = 0; j < 16; j++) v[j] = lds(s, i0 + j*m);
    r16_inv(v, u1);
    #pragma unroll
    for (int j = 0; j < 16; j++) sts(s, i0 + j*m, v[j]);
}

// ---------------- kA: x -> first 16-pt stage -> g_B (transposed) ------------
__global__ void __launch_bounds__(1024) kA(const float2* __restrict__ x2) {
    __shared__ __half2 tile[32][33];
    const int tx = threadIdx.x & 31, ty = threadIdx.x >> 5;
    const int b = blockIdx.z;
    const int pr0 = blockIdx.x * 32, n20 = blockIdx.y * 32;
    const float2* xb = x2 + (size_t)b * SEQ_L * NPAIR;
    const int n2 = n20 + ty;
    C2 v[16];
    #pragma unroll
    for (int j = 0; j < 8; j++) {
        float2 t = __ldg(&xb[(size_t)(j * 1024 + n2) * NPAIR + pr0 + tx]);
        v[j] = mkc(t.x, t.y);
    }
    r16_fwd_zfold(v, twN(n2));
    #pragma unroll
    for (int j = 0; j < 16; j++) {
        __syncthreads();
        tile[ty][tx] = __floats2half2_rn(v[j].x, v[j].y);
        __syncthreads();
        g_B[((size_t)(b * NPAIR + pr0 + ty) * 16 + j) * 1024 + n20 + tx] = tile[tx][ty];
    }
}

// ------- kAf: filt -> first stage -> g_kft (fp32 intermediate) --------------
__global__ void __launch_bounds__(1024) kAf(const float* __restrict__ filt) {
    const int n2 = threadIdx.x, pr = blockIdx.x;
    const float* k0 = filt + (size_t)(2 * pr) * SEQ_L;
    const float* k1 = k0 + SEQ_L;
    C2 v[16];
    #pragma unroll
    for (int j = 0; j < 8; j++) {
        int t = j * 1024 + n2;
        v[j] = mkc(k0[t], k1[t]);
    }
    r16_fwd_zfold(v, twN(n2));
    #pragma unroll
    for (int j = 0; j < 16; j++)
        g_kft[((size_t)pr * 16 + j) * 1024 + n2] = make_float2(v[j].x, v[j].y);
}

// ------ kBf: forward 1024-FFT of filter rows, g_kft(fp32) -> g_kf(half) -----
__global__ void __launch_bounds__(128) kBf() {
    __shared__ float2 s0[ROWLEN], s1[ROWLEN];
    const int t = threadIdx.x;
    const int pr = blockIdx.y, j0 = blockIdx.x * 2;
    const float2* r0 = g_kft + ((size_t)pr * 16 + j0) * 1024;
    const float2* r1 = r0 + 1024;
    __half2* o0 = g_kf + ((size_t)pr * 16 + j0) * 1024;
    __half2* o1 = o0 + 1024;
    for (int i = t; i < 1024; i += 128) { s0[SP2(i)] = r0[i]; s1[SP2(i)] = r1[i]; }
    __syncthreads();
    float2* srow = (t >= 64) ? s1 : s0;
    const int bf = t & 63;
    row_fwd(srow, bf, 6); __syncthreads();
    row_fwd(srow, bf, 2); __syncthreads();
    for (int idx = t; idx < 512; idx += 128) {
        float2* s = (idx & 256) ? s1 : s0;
        __half2* o = (idx & 256) ? o1 : o0;
        int g = idx & 255;
        C2 a = lds(s,4*g), b = lds(s,4*g+1), c = lds(s,4*g+2), d = lds(s,4*g+3);
        fwd4(a, b, c, d);
        o[4*g]   = __floats2half2_rn(a.x, a.y);
        o[4*g+1] = __floats2half2_rn(b.x, b.y);
        o[4*g+2] = __floats2half2_rn(c.x, c.y);
        o[4*g+3] = __floats2half2_rn(d.x, d.y);
    }
}

// ---------------- kB: row FFT + pointwise + row inverse ---------------------
__global__ void __launch_bounds__(128, 8) kB() {
    __shared__ float2 s0[ROWLEN], s1[ROWLEN];
    const int t = threadIdx.x;
    const int b = blockIdx.x & 3, pi = blockIdx.x >> 2, pr = blockIdx.y;
    const int jA = c_jA[pi], jB = c_jB[pi];
    __half2* rA = g_B + ((size_t)(b * NPAIR + pr) * 16 + jA) * 1024;
    __half2* rB = g_B + ((size_t)(b * NPAIR + pr) * 16 + jB) * 1024;
    const __half2* kfA = g_kf + ((size_t)pr * 16 + jA) * 1024;
    const __half2* kfB = g_kf + ((size_t)pr * 16 + jB) * 1024;
    // vectorized load: 2 half2 per 8B transaction
    const float2* rA2 = (const float2*)rA;
    const float2* rB2 = (const float2*)rB;
    for (int i = t; i < 512; i += 128) {
        float2 pa = rA2[i];
        __half2 h0 = *(__half2*)&pa.x, h1 = *(__half2*)&pa.y;
        s0[SP2(2*i)]   = __half22float2(h0);
        s0[SP2(2*i+1)] = __half22float2(h1);
        float2 pb = rB2[i];
        __half2 g0 = *(__half2*)&pb.x, g1 = *(__half2*)&pb.y;
        s1[SP2(2*i)]   = __half22float2(g0);
        s1[SP2(2*i+1)] = __half22float2(g1);
    }
    __syncthreads();
    float2* srow = (t >= 64) ? s1 : s0;
    const int bf = t & 63;
    row_fwd(srow, bf, 6); __syncthreads();
    row_fwd(srow, bf, 2); __syncthreads();

    if (pi) {
        // cross pair: row A pos p  <->  row B pos 1023-p
        #pragma unroll
        for (int gi = 0; gi < 2; gi++) {
            int g = t + gi * 128, g2 = 255 - g;
            C2 a[4], bb[4], ka[4], kb[4];
            #pragma unroll
            for (int s = 0; s < 4; s++) a[s] = lds(s0, 4*g + s);
            fwd4(a[0], a[1], a[2], a[3]);
            #pragma unroll
            for (int s = 0; s < 4; s++) bb[s] = lds(s1, 4*g2 + s);
            fwd4(bb[0], bb[1], bb[2], bb[3]);
            #pragma unroll
            for (int s = 0; s < 4; s++) {
                ka[s] = ldk(kfA, 4*g + s);
                kb[s] = ldk(kfB, 4*g2 + s);
            }
            #pragma unroll
            for (int s = 0; s < 4; s++) pw(a[s], bb[3-s], ka[s], kb[3-s], a[s], bb[3-s]);
            inv4(a[0], a[1], a[2], a[3]);
            inv4(bb[0], bb[1], bb[2], bb[3]);
            #pragma unroll
            for (int s = 0; s < 4; s++) { sts(s0, 4*g + s, a[s]); sts(s1, 4*g2 + s, bb[s]); }
        }
    } else {
        // row s1 = k1=8: self-mirrored, p <-> 1023-p within the row
        {
            int g = t, g2 = 255 - t;
            C2 a[4], bb[4], ka[4], kb[4];
            #pragma unroll
            for (int s = 0; s < 4; s++) a[s] = lds(s1, 4*g + s);
            fwd4(a[0], a[1], a[2], a[3]);
            #pragma unroll
            for (int s = 0; s < 4; s++) bb[s] = lds(s1, 4*g2 + s);
            fwd4(bb[0], bb[1], bb[2], bb[3]);
            #pragma unroll
            for (int s = 0; s < 4; s++) {
                ka[s] = ldk(kfB, 4*g + s);
                kb[s] = ldk(kfB, 4*g2 + s);
            }
            #pragma unroll
            for (int s = 0; s < 4; s++) pw(a[s], bb[3-s], ka[s], kb[3-s], a[s], bb[3-s]);
            inv4(a[0], a[1], a[2], a[3]);
            inv4(bb[0], bb[1], bb[2], bb[3]);
            #pragma unroll
            for (int s = 0; s < 4; s++) { sts(s1, 4*g + s, a[s]); sts(s1, 4*g2 + s, bb[s]); }
        }
        // row s0 = k1=0: complete forward, frequency-indexed pairing, inverse
        for (int g = t; g < 256; g += 128) {
            C2 a = lds(s0,4*g), b2 = lds(s0,4*g+1), c = lds(s0,4*g+2), d = lds(s0,4*g+3);
            fwd4(a, b2, c, d);
            sts(s0,4*g,a); sts(s0,4*g+1,b2); sts(s0,4*g+2,c); sts(s0,4*g+3,d);
        }
        __syncthreads();
        for (int k2 = t; k2 <= 512; k2 += 128) {
            int p  = drev10(k2);
            int p2 = drev10((1024 - k2) & 1023);
            C2 A = lds(s0, p);
            C2 Cv = ldk(kfA, p);
            if (k2 == 0 || k2 == 512) {
                C2 o, dm; pw(A, A, Cv, Cv, o, dm); sts(s0, p, o);
            } else {
                C2 Bv = lds(s0, p2);
                C2 Dv = ldk(kfA, p2);
                C2 oF, oN; pw(A, Bv, Cv, Dv, oF, oN);
                sts(s0, p, oF); sts(s0, p2, oN);
            }
        }
        __syncthreads();
        for (int g = t; g < 256; g += 128) {
            C2 a = lds(s0,4*g), b2 = lds(s0,4*g+1), c = lds(s0,4*g+2), d = lds(s0,4*g+3);
            inv4(a, b2, c, d);
            sts(s0,4*g,a); sts(s0,4*g+1,b2); sts(s0,4*g+2,c); sts(s0,4*g+3,d);
        }
    }
    __syncthreads();
    row_inv(srow, bf, 2); __syncthreads();
    row_inv(srow, bf, 6); __syncthreads();
    // vectorized store: 2 half2 per 8B transaction
    float2* wA2 = (float2*)rA;
    float2* wB2 = (float2*)rB;
    for (int i = t; i < 512; i += 128) {
        float2 a0 = s0[SP2(2*i)], a1 = s0[SP2(2*i+1)];
        float2 oa;
        *(__half2*)&oa.x = __floats2half2_rn(a0.x, a0.y);
        *(__half2*)&oa.y = __floats2half2_rn(a1.x, a1.y);
        wA2[i] = oa;
        float2 b0 = s1[SP2(2*i)], b1 = s1[SP2(2*i+1)];
        float2 ob;
        *(__half2*)&ob.x = __floats2half2_rn(b0.x, b0.y);
        *(__half2*)&ob.y = __floats2half2_rn(b1.x, b1.y);
        wB2[i] = ob;
    }
}

// ---------------- kC: 16-pt inverse stage -> y (transposed write) -----------
__global__ void __launch_bounds__(1024) kC(float2* __restrict__ y2) {
    __shared__ float2 tile[32][33];
    const int tx = threadIdx.x & 31, ty = threadIdx.x >> 5;
    const int b = blockIdx.z;
    const int pr0 = blockIdx.x * 32, n20 = blockIdx.y * 32;
    const int n2 = n20 + tx, pr = pr0 + ty;
    C2 v[16];
    #pragma unroll
    for (int j = 0; j < 16; j++) {
        float2 a = __half22float2(g_B[((size_t)(b * NPAIR + pr) * 16 + j) * 1024 + n2]);
        v[j] = mkc(a.x, a.y);
    }
    r16_inv(v, twN(n2));
    float2* yb = y2 + (size_t)b * SEQ_L * NPAIR;
    #pragma unroll
    for (int j = 0; j < 8; j++) {
        __syncthreads();
        tile[ty][tx] = make_float2(v[j].x, v[j].y);
        __syncthreads();
        yb[(size_t)(j * 1024 + n20 + ty) * NPAIR + pr0 + tx] = tile[tx][ty];
    }
}

// ------------------------------ launch --------------------------------------
extern "C" void kernel_launch(void* const* d_in, const int* in_sizes, int n_in,
                              void* d_out, int out_size) {
    const float* x    = (const float*)d_in[0];
    const float* filt = (const float*)d_in[1];
    if (n_in >= 2 && in_sizes[0] == 2 * NPAIR * SEQ_L &&
        in_sizes[1] == NBATCH * SEQ_L * 2 * NPAIR) {
        const float* t = x; x = filt; filt = t;
    }
    float* out = (float*)d_out;

    kAf<<<NPAIR, 1024>>>(filt);
    kBf<<<dim3(8, NPAIR), 128>>>();
    kA<<<dim3(16, 32, NBATCH), 1024>>>((const float2*)x);
    kB<<<dim3(32, NPAIR), 128>>>();
    kC<<<dim3(16, 32, NBATCH), 1024>>>((float2*)out);
}

// round 14
// speedup vs baseline: 1.6603x; 1.0242x over previous
#include <cuda_runtime.h>
#include <cuda_fp16.h>
#include <math.h>

#define SEQ_L  8192
#define NPAIR  512
#define NBATCH 4
#define FFT_N  16384
#define ROWLEN 1088                 // 1024 + pad
#define SP2(i) ((i) + ((i) >> 4))

// -------- device globals (no cudaMalloc allowed) ----------------------------
__device__ __half2 g_B[(size_t)NBATCH * NPAIR * 16 * 1024];   // 134 MB staging
__device__ __half2 g_kf[(size_t)NPAIR * 16 * 1024];           // 33.5 MB final filter table
__device__ __half2 g_kft[(size_t)NPAIR * 16 * 1024];          // 33.5 MB fp16 intermediate
__constant__ int c_jA[8] = {0, 1, 4, 5, 6, 7, 8, 9};
__constant__ int c_jB[8] = {2, 3, 15, 14, 13, 12, 11, 10};

// ----------------------------- complex helpers ------------------------------
struct C2 { float x, y; };
__device__ __forceinline__ C2 mkc(float a, float b){ C2 r; r.x=a; r.y=b; return r; }
__device__ __forceinline__ C2 cadd(C2 a, C2 b){ return mkc(a.x+b.x, a.y+b.y); }
__device__ __forceinline__ C2 csub(C2 a, C2 b){ return mkc(a.x-b.x, a.y-b.y); }
__device__ __forceinline__ C2 cmul(C2 a, C2 b){ return mkc(a.x*b.x - a.y*b.y, a.x*b.y + a.y*b.x); }
__device__ __forceinline__ C2 cmulc(C2 a, C2 b){ return mkc(a.x*b.x + a.y*b.y, a.y*b.x - a.x*b.y); }
__device__ __forceinline__ C2 mulni(C2 a){ return mkc(a.y, -a.x); }
__device__ __forceinline__ C2 mulpi(C2 a){ return mkc(-a.y, a.x); }

__device__ __forceinline__ C2 w16c(int n) {
    const float C[10] = {1.f, 0.92387953f, 0.70710678f, 0.38268343f, 0.f,
                         -0.38268343f, -0.70710678f, -0.92387953f, -1.f, -0.92387953f};
    const float S[10] = {0.f, -0.38268343f, -0.70710678f, -0.92387953f, -1.f,
                         -0.92387953f, -0.70710678f, -0.38268343f, 0.f, 0.38268343f};
    return mkc(C[n], S[n]);
}
__device__ __forceinline__ C2 twN(int j) {   // W_16384^j
    float sv, cv; sincospif(-(float)j * (1.0f/8192.0f), &sv, &cv); return mkc(cv, sv);
}
__device__ __forceinline__ C2 tw1k(int j) {  // W_1024^j
    float sv, cv; sincospif(-(float)j * (1.0f/512.0f), &sv, &cv); return mkc(cv, sv);
}
// digit-reverse base-4 of 10-bit index (5 digits). Self-inverse.
__device__ __forceinline__ int drev10(int p) {
    unsigned r = __brev((unsigned)p) >> 22;
    return (int)(((r & 0x155u) << 1) | ((r & 0x2AAu) >> 1));
}
// half2 table load -> C2
__device__ __forceinline__ C2 ldk(const __half2* k, int i) {
    float2 t = __half22float2(__ldg(&k[i]));
    return mkc(t.x, t.y);
}

// ---------------- register radix-16 (two fused radix-4 layers) --------------
__device__ __forceinline__ void r16_fwd(C2* v, C2 u1) {
    C2 u2 = cmul(u1,u1);
    C2 u3 = cmul(u2,u1);
    #pragma unroll
    for (int q = 0; q < 4; q++) {
        C2 a=v[q], b=v[q+4], c=v[q+8], d=v[q+12];
        C2 t0=cadd(a,c), t1=csub(a,c), t2=cadd(b,d), t3=mulni(csub(b,d));
        v[q] = cadd(t0,t2);
        C2 o1 = cmul(cadd(t1,t3), u1);
        C2 o2 = cmul(csub(t0,t2), u2);
        C2 o3 = cmul(csub(t1,t3), u3);
        if (q) { o1=cmul(o1,w16c(q)); o2=cmul(o2,w16c(2*q)); o3=cmul(o3,w16c(3*q)); }
        v[q+4]=o1; v[q+8]=o2; v[q+12]=o3;
    }
    C2 u4 = cmul(u2,u2);
    C2 u8 = cmul(u4,u4);
    C2 u12 = cmul(u8,u4);
    #pragma unroll
    for (int s = 0; s < 4; s++) {
        C2 a=v[4*s], b=v[4*s+1], c=v[4*s+2], d=v[4*s+3];
        C2 t0=cadd(a,c), t1=csub(a,c), t2=cadd(b,d), t3=mulni(csub(b,d));
        v[4*s]   = cadd(t0,t2);
        v[4*s+1] = cmul(cadd(t1,t3), u4);
        v[4*s+2] = cmul(csub(t0,t2), u8);
        v[4*s+3] = cmul(csub(t1,t3), u12);
    }
}

__device__ __forceinline__ void r16_fwd_zfold(C2* v, C2 u1) {
    C2 u2 = cmul(u1,u1);
    C2 u3 = cmul(u2,u1);
    #pragma unroll
    for (int q = 0; q < 4; q++) {
        C2 a=v[q], b=v[q+4];
        C2 nb = mulni(b);
        C2 o0 = cadd(a,b);
        C2 o1 = cmul(cadd(a,nb), u1);
        C2 o2 = cmul(csub(a,b), u2);
        C2 o3 = cmul(csub(a,nb), u3);
        if (q) { o1=cmul(o1,w16c(q)); o2=cmul(o2,w16c(2*q)); o3=cmul(o3,w16c(3*q)); }
        v[q]=o0; v[q+4]=o1; v[q+8]=o2; v[q+12]=o3;
    }
    C2 u4 = cmul(u2,u2);
    C2 u8 = cmul(u4,u4);
    C2 u12 = cmul(u8,u4);
    #pragma unroll
    for (int s = 0; s < 4; s++) {
        C2 a=v[4*s], b=v[4*s+1], c=v[4*s+2], d=v[4*s+3];
        C2 t0=cadd(a,c), t1=csub(a,c), t2=cadd(b,d), t3=mulni(csub(b,d));
        v[4*s]   = cadd(t0,t2);
        v[4*s+1] = cmul(cadd(t1,t3), u4);
        v[4*s+2] = cmul(csub(t0,t2), u8);
        v[4*s+3] = cmul(csub(t1,t3), u12);
    }
}

__device__ __forceinline__ void r16_inv(C2* v, C2 u1) {
    C2 u2 = cmul(u1,u1);
    C2 u4 = cmul(u2,u2);
    C2 u8 = cmul(u4,u4);
    C2 u12 = cmul(u8,u4);
    #pragma unroll
    for (int s = 0; s < 4; s++) {
        C2 a = v[4*s];
        C2 b = cmulc(v[4*s+1], u4);
        C2 c = cmulc(v[4*s+2], u8);
        C2 d = cmulc(v[4*s+3], u12);
        C2 p0=cadd(a,c), p1=csub(a,c), p2=cadd(b,d), p3=mulpi(csub(b,d));
        v[4*s]=cadd(p0,p2); v[4*s+1]=cadd(p1,p3); v[4*s+2]=csub(p0,p2); v[4*s+3]=csub(p1,p3);
    }
    C2 u3 = cmul(u2,u1);
    #pragma unroll
    for (int q = 0; q < 4; q++) {
        C2 a = v[q];
        C2 b = cmulc(v[q+4],  u1);
        C2 c = cmulc(v[q+8],  u2);
        C2 d = cmulc(v[q+12], u3);
        if (q) { b=cmulc(b,w16c(q)); c=cmulc(c,w16c(2*q)); d=cmulc(d,w16c(3*q)); }
        C2 p0=cadd(a,c), p1=csub(a,c), p2=cadd(b,d), p3=mulpi(csub(b,d));
        v[q]=cadd(p0,p2); v[q+4]=cadd(p1,p3); v[q+8]=csub(p0,p2); v[q+12]=csub(p1,p3);
    }
}

__device__ __forceinline__ void fwd4(C2& a, C2& b, C2& c, C2& d) {
    C2 t0=cadd(a,c), t1=csub(a,c), t2=cadd(b,d), t3=mulni(csub(b,d));
    a=cadd(t0,t2); b=cadd(t1,t3); c=csub(t0,t2); d=csub(t1,t3);
}
__device__ __forceinline__ void inv4(C2& a, C2& b, C2& c, C2& d) {
    C2 p0=cadd(a,c), p1=csub(a,c), p2=cadd(b,d), p3=mulpi(csub(b,d));
    a=cadd(p0,p2); b=cadd(p1,p3); c=csub(p0,p2); d=csub(p1,p3);
}

// pointwise packed-real product: A=Z[f], Braw=Z[N-f], Cv=Zk[f], Draw=Zk[N-f]
__device__ __forceinline__ void pw(C2 A, C2 Braw, C2 Cv, C2 Draw, C2& outF, C2& outNF) {
    const float s = 1.0f / (4.0f * (float)FFT_N);
    float br = Braw.x, bi = -Braw.y;
    float dr = Draw.x, di = -Draw.y;
    float apbr = A.x + br, apbi = A.y + bi;
    float ambr = A.x - br, ambi = A.y - bi;
    float cpdr = Cv.x + dr, cpdi = Cv.y + di;
    float cmdr = Cv.x - dr, cmdi = Cv.y - di;
    float Pr = apbr * cpdr - apbi * cpdi, Pi = apbr * cpdi + apbi * cpdr;
    float Qr = ambr * cmdr - ambi * cmdi, Qi = ambr * cmdi + ambi * cmdr;
    outF  = mkc((Pr + Qi) * s,  (Pi - Qr) * s);
    outNF = mkc((Pr - Qi) * s, -(Pi + Qr) * s);
}

// --------------------- 1024-point row passes in smem ------------------------
__device__ __forceinline__ C2 lds(const float2* s, int i){ float2 t = s[SP2(i)]; return mkc(t.x,t.y); }
__device__ __forceinline__ void sts(float2* s, int i, C2 v){ s[SP2(i)] = make_float2(v.x,v.y); }

__device__ __forceinline__ void row_fwd(float2* s, int bf, int LM) {
    const int m = 1 << LM;
    const int r = bf & (m - 1);
    const int i0 = ((bf >> LM) << (LM + 4)) + r;
    C2 u1 = tw1k(r << (6 - LM));
    C2 v[16];
    #pragma unroll
    for (int j = 0; j < 16; j++) v[j] = lds(s, i0 + j*m);
    r16_fwd(v, u1);
    #pragma unroll
    for (int j = 0; j < 16; j++) sts(s, i0 + j*m, v[j]);
}
__device__ __forceinline__ void row_inv(float2* s, int bf, int LM) {
    const int m = 1 << LM;
    const int r = bf & (m - 1);
    const int i0 = ((bf >> LM) << (LM + 4)) + r;
    C2 u1 = tw1k(r << (6 - LM));
    C2 v[16];
    #pragma unroll
    for (int j = 0; j < 16; j++) v[j] = lds(s, i0 + j*m);
    r16_inv(v, u1);
    #pragma unroll
    for (int j = 0; j < 16; j++) sts(s, i0 + j*m, v[j]);
}

// ---------------- kA: x -> first 16-pt stage -> g_B (batched transpose) -----
__global__ void __launch_bounds__(1024) kA(const float2* __restrict__ x2) {
    __shared__ __half2 tile[8][32][33];
    const int tx = threadIdx.x & 31, ty = threadIdx.x >> 5;
    const int b = blockIdx.z;
    const int pr0 = blockIdx.x * 32, n20 = blockIdx.y * 32;
    const float2* xb = x2 + (size_t)b * SEQ_L * NPAIR;
    const int n2 = n20 + ty;
    C2 v[16];
    #pragma unroll
    for (int j = 0; j < 8; j++) {
        float2 t = __ldg(&xb[(size_t)(j * 1024 + n2) * NPAIR + pr0 + tx]);
        v[j] = mkc(t.x, t.y);
    }
    r16_fwd_zfold(v, twN(n2));
    #pragma unroll
    for (int h = 0; h < 2; h++) {
        __syncthreads();
        #pragma unroll
        for (int jj = 0; jj < 8; jj++)
            tile[jj][ty][tx] = __floats2half2_rn(v[8*h + jj].x, v[8*h + jj].y);
        __syncthreads();
        #pragma unroll
        for (int jj = 0; jj < 8; jj++)
            g_B[((size_t)(b * NPAIR + pr0 + ty) * 16 + 8*h + jj) * 1024 + n20 + tx] =
                tile[jj][tx][ty];
    }
}

// ------- kAf: filt -> first stage -> g_kft (fp16 intermediate) --------------
__global__ void __launch_bounds__(1024) kAf(const float* __restrict__ filt) {
    const int n2 = threadIdx.x, pr = blockIdx.x;
    const float* k0 = filt + (size_t)(2 * pr) * SEQ_L;
    const float* k1 = k0 + SEQ_L;
    C2 v[16];
    #pragma unroll
    for (int j = 0; j < 8; j++) {
        int t = j * 1024 + n2;
        v[j] = mkc(k0[t], k1[t]);
    }
    r16_fwd_zfold(v, twN(n2));
    #pragma unroll
    for (int j = 0; j < 16; j++)
        g_kft[((size_t)pr * 16 + j) * 1024 + n2] = __floats2half2_rn(v[j].x, v[j].y);
}

// ------ kBf: forward 1024-FFT of filter rows, g_kft(fp16) -> g_kf(fp16) -----
__global__ void __launch_bounds__(128) kBf() {
    __shared__ float2 s0[ROWLEN], s1[ROWLEN];
    const int t = threadIdx.x;
    const int pr = blockIdx.y, j0 = blockIdx.x * 2;
    const __half2* r0 = g_kft + ((size_t)pr * 16 + j0) * 1024;
    const __half2* r1 = r0 + 1024;
    __half2* o0 = g_kf + ((size_t)pr * 16 + j0) * 1024;
    __half2* o1 = o0 + 1024;
    for (int i = t; i < 1024; i += 128) {
        s0[SP2(i)] = __half22float2(r0[i]);
        s1[SP2(i)] = __half22float2(r1[i]);
    }
    __syncthreads();
    float2* srow = (t >= 64) ? s1 : s0;
    const int bf = t & 63;
    row_fwd(srow, bf, 6); __syncthreads();
    row_fwd(srow, bf, 2); __syncthreads();
    for (int idx = t; idx < 512; idx += 128) {
        float2* s = (idx & 256) ? s1 : s0;
        __half2* o = (idx & 256) ? o1 : o0;
        int g = idx & 255;
        C2 a = lds(s,4*g), b = lds(s,4*g+1), c = lds(s,4*g+2), d = lds(s,4*g+3);
        fwd4(a, b, c, d);
        o[4*g]   = __floats2half2_rn(a.x, a.y);
        o[4*g+1] = __floats2half2_rn(b.x, b.y);
        o[4*g+2] = __floats2half2_rn(c.x, c.y);
        o[4*g+3] = __floats2half2_rn(d.x, d.y);
    }
}

// ---------------- kB: row FFT + pointwise + row inverse ---------------------
__global__ void __launch_bounds__(128, 8) kB() {
    __shared__ float2 s0[ROWLEN], s1[ROWLEN];
    const int t = threadIdx.x;
    const int b = blockIdx.x & 3, pi = blockIdx.x >> 2, pr = blockIdx.y;
    const int jA = c_jA[pi], jB = c_jB[pi];
    __half2* rA = g_B + ((size_t)(b * NPAIR + pr) * 16 + jA) * 1024;
    __half2* rB = g_B + ((size_t)(b * NPAIR + pr) * 16 + jB) * 1024;
    const __half2* kfA = g_kf + ((size_t)pr * 16 + jA) * 1024;
    const __half2* kfB = g_kf + ((size_t)pr * 16 + jB) * 1024;
    // vectorized load: 2 half2 per 8B transaction
    const float2* rA2 = (const float2*)rA;
    const float2* rB2 = (const float2*)rB;
    for (int i = t; i < 512; i += 128) {
        float2 pa = rA2[i];
        __half2 h0 = *(__half2*)&pa.x, h1 = *(__half2*)&pa.y;
        s0[SP2(2*i)]   = __half22float2(h0);
        s0[SP2(2*i+1)] = __half22float2(h1);
        float2 pb = rB2[i];
        __half2 g0 = *(__half2*)&pb.x, g1 = *(__half2*)&pb.y;
        s1[SP2(2*i)]   = __half22float2(g0);
        s1[SP2(2*i+1)] = __half22float2(g1);
    }
    __syncthreads();
    float2* srow = (t >= 64) ? s1 : s0;
    const int bf = t & 63;
    row_fwd(srow, bf, 6); __syncthreads();
    row_fwd(srow, bf, 2); __syncthreads();

    if (pi) {
        // cross pair: row A pos p  <->  row B pos 1023-p
        #pragma unroll
        for (int gi = 0; gi < 2; gi++) {
            int g = t + gi * 128, g2 = 255 - g;
            C2 a[4], bb[4], ka[4], kb[4];
            #pragma unroll
            for (int s = 0; s < 4; s++) a[s] = lds(s0, 4*g + s);
            fwd4(a[0], a[1], a[2], a[3]);
            #pragma unroll
            for (int s = 0; s < 4; s++) bb[s] = lds(s1, 4*g2 + s);
            fwd4(bb[0], bb[1], bb[2], bb[3]);
            #pragma unroll
            for (int s = 0; s < 4; s++) {
                ka[s] = ldk(kfA, 4*g + s);
                kb[s] = ldk(kfB, 4*g2 + s);
            }
            #pragma unroll
            for (int s = 0; s < 4; s++) pw(a[s], bb[3-s], ka[s], kb[3-s], a[s], bb[3-s]);
            inv4(a[0], a[1], a[2], a[3]);
            inv4(bb[0], bb[1], bb[2], bb[3]);
            #pragma unroll
            for (int s = 0; s < 4; s++) { sts(s0, 4*g + s, a[s]); sts(s1, 4*g2 + s, bb[s]); }
        }
    } else {
        // row s1 = k1=8: self-mirrored, p <-> 1023-p within the row
        {
            int g = t, g2 = 255 - t;
            C2 a[4], bb[4], ka[4], kb[4];
            #pragma unroll
            for (int s = 0; s < 4; s++) a[s] = lds(s1, 4*g + s);
            fwd4(a[0], a[1], a[2], a[3]);
            #pragma unroll
            for (int s = 0; s < 4; s++) bb[s] = lds(s1, 4*g2 + s);
            fwd4(bb[0], bb[1], bb[2], bb[3]);
            #pragma unroll
            for (int s = 0; s < 4; s++) {
                ka[s] = ldk(kfB, 4*g + s);
                kb[s] = ldk(kfB, 4*g2 + s);
            }
            #pragma unroll
            for (int s = 0; s < 4; s++) pw(a[s], bb[3-s], ka[s], kb[3-s], a[s], bb[3-s]);
            inv4(a[0], a[1], a[2], a[3]);
            inv4(bb[0], bb[1], bb[2], bb[3]);
            #pragma unroll
            for (int s = 0; s < 4; s++) { sts(s1, 4*g + s, a[s]); sts(s1, 4*g2 + s, bb[s]); }
        }
        // row s0 = k1=0: complete forward, frequency-indexed pairing, inverse
        for (int g = t; g < 256; g += 128) {
            C2 a = lds(s0,4*g), b2 = lds(s0,4*g+1), c = lds(s0,4*g+2), d = lds(s0,4*g+3);
            fwd4(a, b2, c, d);
            sts(s0,4*g,a); sts(s0,4*g+1,b2); sts(s0,4*g+2,c); sts(s0,4*g+3,d);
        }
        __syncthreads();
        for (int k2 = t; k2 <= 512; k2 += 128) {
            int p  = drev10(k2);
            int p2 = drev10((1024 - k2) & 1023);
            C2 A = lds(s0, p);
            C2 Cv = ldk(kfA, p);
            if (k2 == 0 || k2 == 512) {
                C2 o, dm; pw(A, A, Cv, Cv, o, dm); sts(s0, p, o);
            } else {
                C2 Bv = lds(s0, p2);
                C2 Dv = ldk(kfA, p2);
                C2 oF, oN; pw(A, Bv, Cv, Dv, oF, oN);
                sts(s0, p, oF); sts(s0, p2, oN);
            }
        }
        __syncthreads();
        for (int g = t; g < 256; g += 128) {
            C2 a = lds(s0,4*g), b2 = lds(s0,4*g+1), c = lds(s0,4*g+2), d = lds(s0,4*g+3);
            inv4(a, b2, c, d);
            sts(s0,4*g,a); sts(s0,4*g+1,b2); sts(s0,4*g+2,c); sts(s0,4*g+3,d);
        }
    }
    __syncthreads();
    row_inv(srow, bf, 2); __syncthreads();
    row_inv(srow, bf, 6); __syncthreads();
    // vectorized store: 2 half2 per 8B transaction
    float2* wA2 = (float2*)rA;
    float2* wB2 = (float2*)rB;
    for (int i = t; i < 512; i += 128) {
        float2 a0 = s0[SP2(2*i)], a1 = s0[SP2(2*i+1)];
        float2 oa;
        *(__half2*)&oa.x = __floats2half2_rn(a0.x, a0.y);
        *(__half2*)&oa.y = __floats2half2_rn(a1.x, a1.y);
        wA2[i] = oa;
        float2 b0 = s1[SP2(2*i)], b1 = s1[SP2(2*i+1)];
        float2 ob;
        *(__half2*)&ob.x = __floats2half2_rn(b0.x, b0.y);
        *(__half2*)&ob.y = __floats2half2_rn(b1.x, b1.y);
        wB2[i] = ob;
    }
}

// ---------------- kC: 16-pt inverse stage -> y (batched transpose) ----------
__global__ void __launch_bounds__(1024) kC(float2* __restrict__ y2) {
    __shared__ float2 tile[4][32][33];
    const int tx = threadIdx.x & 31, ty = threadIdx.x >> 5;
    const int b = blockIdx.z;
    const int pr0 = blockIdx.x * 32, n20 = blockIdx.y * 32;
    const int n2 = n20 + tx, pr = pr0 + ty;
    C2 v[16];
    #pragma unroll
    for (int j = 0; j < 16; j++) {
        float2 a = __half22float2(g_B[((size_t)(b * NPAIR + pr) * 16 + j) * 1024 + n2]);
        v[j] = mkc(a.x, a.y);
    }
    r16_inv(v, twN(n2));
    float2* yb = y2 + (size_t)b * SEQ_L * NPAIR;
    #pragma unroll
    for (int h = 0; h < 2; h++) {
        __syncthreads();
        #pragma unroll
        for (int jj = 0; jj < 4; jj++)
            tile[jj][ty][tx] = make_float2(v[4*h + jj].x, v[4*h + jj].y);
        __syncthreads();
        #pragma unroll
        for (int jj = 0; jj < 4; jj++)
            yb[(size_t)((4*h + jj) * 1024 + n20 + ty) * NPAIR + pr0 + tx] = tile[jj][tx][ty];
    }
}

// ------------------------------ launch --------------------------------------
extern "C" void kernel_launch(void* const* d_in, const int* in_sizes, int n_in,
                              void* d_out, int out_size) {
    const float* x    = (const float*)d_in[0];
    const float* filt = (const float*)d_in[1];
    if (n_in >= 2 && in_sizes[0] == 2 * NPAIR * SEQ_L &&
        in_sizes[1] == NBATCH * SEQ_L * 2 * NPAIR) {
        const float* t = x; x = filt; filt = t;
    }
    float* out = (float*)d_out;

    kAf<<<NPAIR, 1024>>>(filt);
    kBf<<<dim3(8, NPAIR), 128>>>();
    kA<<<dim3(16, 32, NBATCH), 1024>>>((const float2*)x);
    kB<<<dim3(32, NPAIR), 128>>>();
    kC<<<dim3(16, 32, NBATCH), 1024>>>((float2*)out);
}